// round 17
// baseline (speedup 1.0000x reference)
#include <cuda_runtime.h>
#include <math.h>

#define RESN   320
#define MTRAJ  25600
#define NB     16
#define OSN    400
#define GL     8
#define LSTR   12   /* lane-stride in floats: 48B, keeps every row 16B-aligned */

#define BETA_F  6.99665877f      /* pi*sqrt(4.96) */
#define BETA2_F 48.9532378f      /* pi^2*4.96 */

typedef unsigned long long u64;

/* batch-innermost scratch: g_grid[(cell)*NB + b], g_T1[(yout*OSN + x)*NB + b] (complex) */
__device__ __align__(16) float g_grid[OSN * OSN * NB * 2];
__device__ __align__(16) float g_T1[RESN * OSN * NB * 2];
__device__ __align__(16) float2 g_E[OSN];
__device__ __align__(16) float  g_apod[RESN];

/* ---------------- packed f32x2 helpers ---------------- */
__device__ __forceinline__ u64 dup2(float x) {
    u64 r; asm("mov.b64 %0, {%1, %1};" : "=l"(r) : "f"(x)); return r;
}
__device__ __forceinline__ void unpack2(u64 p, float& lo, float& hi) {
    asm("mov.b64 {%0, %1}, %2;" : "=f"(lo), "=f"(hi) : "l"(p));
}
__device__ __forceinline__ u64 fma2(u64 a, u64 b, u64 c) {
    u64 d; asm("fma.rn.f32x2 %0, %1, %2, %3;" : "=l"(d) : "l"(a), "l"(b), "l"(c)); return d;
}

__device__ __forceinline__ void red_add_v4(float* p, float a, float b, float c, float d) {
    asm volatile("red.global.add.v4.f32 [%0], {%1, %2, %3, %4};"
                 :: "l"(p), "f"(a), "f"(b), "f"(c), "f"(d) : "memory");
}

/* ---------------- Bessel I0 (A&S 9.8.1 / 9.8.2) ---------------- */
__device__ __forceinline__ float i0f_dev(float x) {
    if (x < 3.75f) {
        float t = x * (1.0f / 3.75f);
        t *= t;
        return 1.0f + t * (3.5156229f + t * (3.0899424f + t * (1.2067492f
             + t * (0.2659732f + t * (0.0360768f + t * 0.0045813f)))));
    } else {
        float t = 3.75f / x;
        float p = 0.39894228f + t * (0.01328592f + t * (0.00225319f + t * (-0.00157565f
                + t * (0.00916281f + t * (-0.02057706f + t * (0.02635537f
                + t * (-0.01647633f + t * 0.00392377f)))))));
        return expf(x) * rsqrtf(x) * p;
    }
}

__device__ __forceinline__ float kbw(float delta) {
    float u  = delta * 0.5f;
    float tt = fmaxf(1.0f - u * u, 0.0f);
    return i0f_dev(BETA_F * sqrtf(tt)) * 0.25f;
}

/* ------ kernel 1: zero the scatter grid + build twiddle/apod tables ------ */
__global__ void zero_grid_kernel() {
    int i = blockIdx.x * blockDim.x + threadIdx.x;
    if (i < OSN * OSN * NB * 2 / 4)
        ((float4*)g_grid)[i] = make_float4(0.f, 0.f, 0.f, 0.f);
    if (blockIdx.x == 0) {
        for (int k = threadIdx.x; k < OSN; k += blockDim.x) {
            float sv, cv;
            sincospif((float)k * (1.0f / 200.0f), &sv, &cv);
            g_E[k] = make_float2(cv, sv);
        }
        for (int k = threadIdx.x; k < RESN; k += blockDim.x) {
            float d = (float)(k - 160) * 0.0314159265f;
            float a = sqrtf(fmaxf(BETA2_F - d * d, 1e-12f));
            g_apod[k] = a / sinhf(a);
        }
    }
}

/* -- kernel 2: bilinear sample + KB scatter, thread = (point, batch-pair) -- */
__global__ void grid_scatter_kernel(const float* __restrict__ ksp,
                                    const float* __restrict__ traj) {
    int idx = blockIdx.x * blockDim.x + threadIdx.x;
    if (idx >= MTRAJ * 8) return;
    int bp = idx & 7;          /* batch pair: handles b = 2bp, 2bp+1 */
    int m  = idx >> 3;

    float t0 = traj[2 * m + 0];
    float t1 = traj[2 * m + 1];

    float px = (t0 * (1.0f / 160.0f) + 1.0f) * 0.5f * 319.0f;
    float py = (t1 * (1.0f / 160.0f) + 1.0f) * 0.5f * 319.0f;
    float x0f = floorf(px), y0f = floorf(py);
    float wx1 = px - x0f,   wy1 = py - y0f;
    int   x0  = (int)x0f,   y0  = (int)y0f;

    const float* img0 = ksp + (size_t)(2 * bp) * (RESN * RESN * 2);
    const float* img1 = img0 + RESN * RESN * 2;
    float yr0 = 0.f, yi0 = 0.f, yr1 = 0.f, yi1 = 0.f;
#pragma unroll
    for (int dy = 0; dy < 2; dy++) {
#pragma unroll
        for (int dx = 0; dx < 2; dx++) {
            int  xi  = x0 + dx, yv = y0 + dy;
            float w  = (dx ? wx1 : 1.0f - wx1) * (dy ? wy1 : 1.0f - wy1);
            bool inb = (xi >= 0) && (xi < RESN) && (yv >= 0) && (yv < RESN);
            int  xc  = min(max(xi, 0), RESN - 1);
            int  yc  = min(max(yv, 0), RESN - 1);
            size_t off = ((size_t)yc * RESN + xc) * 2;
            float2 v0 = *(const float2*)(img0 + off);
            float2 v1 = *(const float2*)(img1 + off);
            float wm = inb ? w : 0.0f;
            yr0 += v0.x * wm;  yi0 += v0.y * wm;
            yr1 += v1.x * wm;  yi1 += v1.y * wm;
        }
    }

    float cy = t0 * 1.25f + 200.0f;
    float cx = t1 * 1.25f + 200.0f;
    int sy = (int)ceilf(cy - 2.0f);
    int sx = (int)ceilf(cx - 2.0f);

    float wy[4], wx[4];
    int   iy[4], ix[4];
#pragma unroll
    for (int j = 0; j < 4; j++) {
        wy[j] = kbw(cy - (float)(sy + j));
        wx[j] = kbw(cx - (float)(sx + j));
        int a = sy + j; if (a < 0) a += OSN; if (a >= OSN) a -= OSN; iy[j] = a;
        int c = sx + j; if (c < 0) c += OSN; if (c >= OSN) c -= OSN; ix[j] = c;
    }

    float* gb = g_grid + 4 * bp;
#pragma unroll
    for (int jy = 0; jy < 4; jy++) {
#pragma unroll
        for (int jx = 0; jx < 4; jx++) {
            float w = wy[jy] * wx[jx];
            float* cell = gb + ((size_t)iy[jy] * OSN + ix[jx]) * (NB * 2);
            red_add_v4(cell, yr0 * w, yi0 * w, yr1 * w, yi1 * w);
        }
    }
}

/* ------------- centered 400-pt DFT as 4-stage radix (5,4,5,4) -------------
   out[n] = (-1)^n * StdDFT400( x[m]*(-1)^m )[n+40],  E[p] = exp(+2i*pi*p/400)
   (-1)^m = (-1)^{m mod 20 parity} propagates to a per-b sign in stage D,
   folded into the stage-D twiddle index (u+200); (-1)^n folds into the store.
   Stages (all twiddles are exact integer indices into E):
     A (r=5): t=(c=t/5, d=t%5); TA[slot t] = sum_a in[c+80a] * E[(80 d a)%400]
     B (r=4): t=(m2=t/20, q=t%20); S[slot t] = sum_b TA[100b+5m2+(q%5)] * E[(20 q b)%400]
     C (r=5): key=t/5 (b=key/20,v20=key%20), vh=t%5, v=20vh+v20;
              U[slot 100b+v] = sum_a S[80a+key] * E[((80vh+4v20) a)%400]
     D (r=4): t<320: u=t+40, v=u%100, s=(t+240)%400;
              X = sum_b U[100b+v] * E[(s b)%400]
   In-place smem with read/sync/write/sync per stage; __maxnreg__(48) holds
   3 CTAs/SM.
--------------------------------------------------------------------------- */

struct DftAcc { u64 X[4]; u64 Y[4]; };

#define DFT_MACR(A, bx, by, baseslot, stride, r, sstep, Et)                      \
    {                                                                            \
        int p_ = 0;                                                              \
        _Pragma("unroll")                                                        \
        for (int k_ = 0; k_ < (r); k_++) {                                       \
            float2 tw = (Et)[p_];                                                \
            p_ += (sstep); if (p_ >= OSN) p_ -= OSN;                             \
            u64 wxp  = dup2(tw.x);                                               \
            u64 wyp  = dup2(tw.y);                                               \
            u64 nwyp = dup2(-tw.y);                                              \
            const float* px_ = (bx) + ((baseslot) + k_ * (stride)) * LSTR;       \
            const float* py_ = (by) + ((baseslot) + k_ * (stride)) * LSTR;       \
            ulonglong2 aX0 = *(const ulonglong2*)(px_);                          \
            ulonglong2 aY0 = *(const ulonglong2*)(py_);                          \
            ulonglong2 aX1 = *(const ulonglong2*)(px_ + 4);                      \
            ulonglong2 aY1 = *(const ulonglong2*)(py_ + 4);                      \
            A.X[0] = fma2(aY0.x, nwyp, fma2(aX0.x, wxp, A.X[0]));                \
            A.Y[0] = fma2(aY0.x, wxp,  fma2(aX0.x, wyp, A.Y[0]));                \
            A.X[1] = fma2(aY0.y, nwyp, fma2(aX0.y, wxp, A.X[1]));                \
            A.Y[1] = fma2(aY0.y, wxp,  fma2(aX0.y, wyp, A.Y[1]));                \
            A.X[2] = fma2(aY1.x, nwyp, fma2(aX1.x, wxp, A.X[2]));                \
            A.Y[2] = fma2(aY1.x, wxp,  fma2(aX1.x, wyp, A.Y[2]));                \
            A.X[3] = fma2(aY1.y, nwyp, fma2(aX1.y, wxp, A.X[3]));                \
            A.Y[3] = fma2(aY1.y, wxp,  fma2(aX1.y, wyp, A.Y[3]));                \
        }                                                                        \
    }

#define ACC_CLEAR(A) { _Pragma("unroll") for (int p = 0; p < 4; p++) { A.X[p] = 0; A.Y[p] = 0; } }

#define ACC_STORE(A, xs_x, xs_y, slot)                                           \
    {                                                                            \
        int srow_ = (slot) * LSTR;                                               \
        _Pragma("unroll")                                                        \
        for (int p = 0; p < 4; p++) {                                            \
            *(u64*)((xs_x) + srow_ + 2 * p) = A.X[p];                            \
            *(u64*)((xs_y) + srow_ + 2 * p) = A.Y[p];                            \
        }                                                                        \
    }

/* stages A,B,C shared by both passes (all 400 threads) */
#define DFT_STAGES_ABC(xs_x, xs_y, E, t)                                         \
    {                                                                            \
        DftAcc A_;                                                               \
        /* stage A: radix-5 */                                                   \
        ACC_CLEAR(A_);                                                           \
        { int c = (t) / 5, d = (t) % 5;                                          \
          DFT_MACR(A_, xs_x, xs_y, c, 80, 5, 80 * d, E); }                       \
        __syncthreads();                                                         \
        ACC_STORE(A_, xs_x, xs_y, t);                                            \
        __syncthreads();                                                         \
        /* stage B: radix-4 */                                                   \
        ACC_CLEAR(A_);                                                           \
        { int m2 = (t) / 20, q = (t) % 20;                                       \
          DFT_MACR(A_, xs_x, xs_y, 5 * m2 + q % 5, 100, 4, 20 * q, E); }         \
        __syncthreads();                                                         \
        ACC_STORE(A_, xs_x, xs_y, t);                                            \
        __syncthreads();                                                         \
        /* stage C: radix-5 */                                                   \
        ACC_CLEAR(A_);                                                           \
        { int key = (t) / 5, vh = (t) % 5;                                       \
          int sC = 80 * vh + 4 * (key % 20);                                     \
          DFT_MACR(A_, xs_x, xs_y, key, 80, 5, sC, E);                           \
          __syncthreads();                                                       \
          ACC_STORE(A_, xs_x, xs_y, 100 * (key / 20) + 20 * vh + (key % 20)); }  \
        __syncthreads();                                                         \
    }

/* pass 1: DFT over y for grid column x; 8 batch lanes per block */
__global__ void __maxnreg__(48) row_dft_kernel() {
    extern __shared__ float sh[];
    float*  xs_x = sh;
    float*  xs_y = sh + OSN * LSTR;
    float2* E    = (float2*)(sh + 2 * OSN * LSTR);

    int t  = threadIdx.x;                   /* 0..399 = y */
    int x  = blockIdx.x >> 1;
    int b0 = (blockIdx.x & 1) * 8;

    const float4* gp4 = (const float4*)(g_grid + (((size_t)t * OSN + x) * NB + b0) * 2);
#pragma unroll
    for (int k = 0; k < 4; k++) {
        float4 v = gp4[k];                  /* batches b0+2k, b0+2k+1 */
        xs_x[t * LSTR + 2 * k]     = v.x;
        xs_y[t * LSTR + 2 * k]     = v.y;
        xs_x[t * LSTR + 2 * k + 1] = v.z;
        xs_y[t * LSTR + 2 * k + 1] = v.w;
    }
    E[t] = g_E[t];
    __syncthreads();

    DFT_STAGES_ABC(xs_x, xs_y, E, t);

    /* stage D: radix-4, only 320 outputs (crop), sign (-1)^t folded in */
    if (t < RESN) {
        int v = (t + 40) % 100;
        int sD = t + 240; if (sD >= OSN) sD -= OSN;
        DftAcc B_;
        ACC_CLEAR(B_);
        DFT_MACR(B_, xs_x, xs_y, v, 100, 4, sD, E);

        u64 sgn = (t & 1) ? 0x8000000080000000ULL : 0ULL;
        float4* Tv = (float4*)(g_T1 + (((size_t)t * OSN + x) * NB + b0) * 2);
#pragma unroll
        for (int p = 0; p < 4; p++) {
            float xr0, xr1, xi0, xi1;
            unpack2(B_.X[p] ^ sgn, xr0, xr1);
            unpack2(B_.Y[p] ^ sgn, xi0, xi1);
            Tv[p] = make_float4(xr0, xi0, xr1, xi1);
        }
    }
}

/* pass 2: DFT over x for output row y_out; coalesced loads + stores */
__global__ void __maxnreg__(48) col_dft_kernel(float* __restrict__ out) {
    extern __shared__ float sh[];
    float*  xs_x = sh;
    float*  xs_y = sh + OSN * LSTR;
    float2* E    = (float2*)(sh + 2 * OSN * LSTR);
    float*  apod = sh + 2 * OSN * LSTR + 2 * OSN;

    int t  = threadIdx.x;                   /* 0..399 = x */
    int yo = blockIdx.x >> 1;
    int b0 = (blockIdx.x & 1) * 8;

    const float4* Tp4 = (const float4*)(g_T1 + (((size_t)yo * OSN + t) * NB + b0) * 2);
#pragma unroll
    for (int k = 0; k < 4; k++) {
        float4 v = Tp4[k];
        xs_x[t * LSTR + 2 * k]     = v.x;
        xs_y[t * LSTR + 2 * k]     = v.y;
        xs_x[t * LSTR + 2 * k + 1] = v.z;
        xs_y[t * LSTR + 2 * k + 1] = v.w;
    }
    E[t] = g_E[t];
    if (t < RESN) apod[t] = g_apod[t];
    __syncthreads();

    DFT_STAGES_ABC(xs_x, xs_y, E, t);

    /* stage D + apodization + coalesced final store; (-1)^t folded into f */
    if (t < RESN) {
        int v = (t + 40) % 100;
        int sD = t + 240; if (sD >= OSN) sD -= OSN;
        DftAcc B_;
        ACC_CLEAR(B_);
        DFT_MACR(B_, xs_x, xs_y, v, 100, 4, sD, E);

        float f = apod[t] * apod[yo] * (1.0f / 320.0f);
        if (t & 1) f = -f;

        float xr[GL], xi[GL];
#pragma unroll
        for (int p = 0; p < 4; p++) {
            unpack2(B_.X[p], xr[2 * p], xr[2 * p + 1]);
            unpack2(B_.Y[p], xi[2 * p], xi[2 * p + 1]);
        }

#pragma unroll
        for (int l = 0; l < GL; l++) {
            int b = b0 + l;
            float* po = out + (((size_t)b * 2) * RESN + yo) * RESN + t;
            po[0]               = xr[l] * f;
            po[RESN * RESN]     = xi[l] * f;
        }
    }
}

extern "C" void kernel_launch(void* const* d_in, const int* in_sizes, int n_in,
                              void* d_out, int out_size) {
    const float* ksp  = (const float*)d_in[0];
    const float* traj = (const float*)d_in[1];
    float* out = (float*)d_out;

    const int SMEM_ROW = (2 * OSN * LSTR + 2 * OSN) * (int)sizeof(float);   /* 41600 B */
    const int SMEM_COL = SMEM_ROW + RESN * (int)sizeof(float);              /* 42880 B */

    cudaFuncSetAttribute(row_dft_kernel, cudaFuncAttributeMaxDynamicSharedMemorySize, SMEM_ROW);
    cudaFuncSetAttribute(col_dft_kernel, cudaFuncAttributeMaxDynamicSharedMemorySize, SMEM_COL);

    zero_grid_kernel<<<(OSN * OSN * NB * 2 / 4 + 255) / 256, 256>>>();
    grid_scatter_kernel<<<(MTRAJ * 8 + 255) / 256, 256>>>(ksp, traj);
    row_dft_kernel<<<OSN * 2, OSN, SMEM_ROW>>>();
    col_dft_kernel<<<RESN * 2, OSN, SMEM_COL>>>(out);
}